// round 4
// baseline (speedup 1.0000x reference)
#include <cuda_runtime.h>
#include <math.h>

#define D      2048
#define RNK    32
#define NST    16
#define LAYER  11
#define GRID   128
#define NTHR   256

// Scratch (device globals; persists across graph replays)
__device__ float g_z1[3][D];
__device__ float g_u[2][3][D];              // [0]=f (fconv), [1]=bw (bconv)
__device__ float g_dbc[2][3][64];
__device__ unsigned long long g_bar;         // monotonic grid barrier counter

__device__ __forceinline__ float warp_sum(float v) {    // result in lane 0
    v += __shfl_down_sync(0xffffffffu, v, 16);
    v += __shfl_down_sync(0xffffffffu, v, 8);
    v += __shfl_down_sync(0xffffffffu, v, 4);
    v += __shfl_down_sync(0xffffffffu, v, 2);
    v += __shfl_down_sync(0xffffffffu, v, 1);
    return v;
}
__device__ __forceinline__ float warp_sum_all(float v) { // result in ALL lanes
    v += __shfl_xor_sync(0xffffffffu, v, 16);
    v += __shfl_xor_sync(0xffffffffu, v, 8);
    v += __shfl_xor_sync(0xffffffffu, v, 4);
    v += __shfl_xor_sync(0xffffffffu, v, 2);
    v += __shfl_xor_sync(0xffffffffu, v, 1);
    return v;
}

// Grid-wide barrier: monotonic counter, round-up-to-multiple target.
// Safe across graph replays (counter never resets; 64-bit won't wrap).
// All GRID blocks are co-resident (GRID=128 < 148 SMs, 1 small block/SM).
__device__ __forceinline__ void grid_bar() {
    __syncthreads();
    if (threadIdx.x == 0) {
        __threadfence();   // publish this block's writes
        unsigned long long my = atomicAdd(&g_bar, 1ull) + 1ull;
        unsigned long long target = ((my + (GRID - 1ull)) / GRID) * GRID;
        volatile unsigned long long* p = (volatile unsigned long long*)&g_bar;
        while (*p < target) { }
        __threadfence();   // acquire: order subsequent reads
    }
    __syncthreads();
}

__device__ __forceinline__ float softplus_f(float v) {
    return fmaxf(v, 0.f) + log1pf(expf(-fabsf(v)));
}

// ---------------------------------------------------------------------------
// Single persistent kernel, 4 phases separated by grid barriers.
// ---------------------------------------------------------------------------
__global__ void __launch_bounds__(NTHR) k_all(
        const float* __restrict__ x,
        const float* __restrict__ gam,
        const float* __restrict__ bet,
        const float* __restrict__ Wp,  const float* __restrict__ bp,
        const float* __restrict__ Wf,  const float* __restrict__ bf,
        const float* __restrict__ Wb,  const float* __restrict__ bb_,
        const float* __restrict__ Wdbc,
        const float* __restrict__ dtp_w,
        const float* __restrict__ dtp_b,
        const float* __restrict__ Dp,
        float* __restrict__ out) {
    __shared__ float s_in[3][D];         // 24 KB staging (xn, then z1)
    __shared__ float red[8][6];
    __shared__ float mu_s[3], inv_s[3];
    __shared__ float s_dbc[2][3][64];
    __shared__ float s_bc[2][3];

    const int tid  = threadIdx.x;
    const int w    = tid >> 5;
    const int l    = tid & 31;
    const int blk  = blockIdx.x;

    // ===================== Phase A: layernorm + proj ========================
    {
        float sm[3] = {0.f, 0.f, 0.f}, sq[3] = {0.f, 0.f, 0.f};
        for (int i = tid; i < D; i += NTHR) {
            #pragma unroll
            for (int b = 0; b < 3; b++) {
                float v = x[b * D + i];
                s_in[b][i] = v;
                sm[b] += v;
                sq[b] += v * v;
            }
        }
        #pragma unroll
        for (int b = 0; b < 3; b++) { sm[b] = warp_sum(sm[b]); sq[b] = warp_sum(sq[b]); }
        if (l == 0) {
            #pragma unroll
            for (int b = 0; b < 3; b++) { red[w][b] = sm[b]; red[w][3 + b] = sq[b]; }
        }
        __syncthreads();
        if (tid < 3) {
            float S = 0.f, Q = 0.f;
            #pragma unroll
            for (int i = 0; i < 8; i++) { S += red[i][tid]; Q += red[i][3 + tid]; }
            float mu = S * (1.f / D);
            float var = Q * (1.f / D) - mu * mu;
            mu_s[tid] = mu;
            inv_s[tid] = rsqrtf(var + 1e-5f);
        }
        __syncthreads();
        const float m0 = mu_s[0], m1 = mu_s[1], m2 = mu_s[2];
        const float i0 = inv_s[0], i1 = inv_s[1], i2 = inv_s[2];
        for (int i = tid; i < D; i += NTHR) {
            const float g = gam[i], be = bet[i];
            s_in[0][i] = (s_in[0][i] - m0) * i0 * g + be;
            s_in[1][i] = (s_in[1][i] - m1) * i1 * g + be;
            s_in[2][i] = (s_in[2][i] - m2) * i2 * g + be;
        }
        __syncthreads();

        // 2 rows/warp -> 16 rows/block -> 2048 rows
        const int row = blk * 16 + w * 2;
        const float4* wa4 = (const float4*)(Wp + (size_t)row * D);
        const float4* wb4 = (const float4*)(Wp + (size_t)(row + 1) * D);
        const float4* x0 = (const float4*)s_in[0];
        const float4* x1 = (const float4*)s_in[1];
        const float4* x2 = (const float4*)s_in[2];
        float a0 = 0.f, a1 = 0.f, a2 = 0.f, b0 = 0.f, b1 = 0.f, b2 = 0.f;
        #pragma unroll
        for (int it = 0; it < 16; it++) {
            const int idx = it * 32 + l;
            float4 wa = wa4[idx], wb = wb4[idx];
            float4 v0 = x0[idx], v1 = x1[idx], v2 = x2[idx];
            a0 += wa.x*v0.x + wa.y*v0.y + wa.z*v0.z + wa.w*v0.w;
            a1 += wa.x*v1.x + wa.y*v1.y + wa.z*v1.z + wa.w*v1.w;
            a2 += wa.x*v2.x + wa.y*v2.y + wa.z*v2.z + wa.w*v2.w;
            b0 += wb.x*v0.x + wb.y*v0.y + wb.z*v0.z + wb.w*v0.w;
            b1 += wb.x*v1.x + wb.y*v1.y + wb.z*v1.z + wb.w*v1.w;
            b2 += wb.x*v2.x + wb.y*v2.y + wb.z*v2.z + wb.w*v2.w;
        }
        a0 = warp_sum(a0); a1 = warp_sum(a1); a2 = warp_sum(a2);
        b0 = warp_sum(b0); b1 = warp_sum(b1); b2 = warp_sum(b2);
        if (l == 0) {
            const float bsa = bp[row], bsb = bp[row + 1];
            g_z1[0][row] = a0 + bsa;  g_z1[0][row + 1] = b0 + bsb;
            g_z1[1][row] = a1 + bsa;  g_z1[1][row + 1] = b1 + bsb;
            g_z1[2][row] = a2 + bsa;  g_z1[2][row + 1] = b2 + bsb;
        }
    }
    grid_bar();

    // ===================== Phase B: f/b conv matvecs ========================
    {
        const float* src = &g_z1[0][0];
        for (int i = tid; i < 3 * D; i += NTHR)
            (&s_in[0][0])[i] = src[i];
        __syncthreads();

        const int which = (blk >= 64) ? 1 : 0;
        const int row = (blk & 63) * 32 + w * 4;   // 4 rows/warp
        const float* W = which ? Wb : Wf;
        const float* bias = which ? bb_ : bf;

        const float4* wr4[4];
        #pragma unroll
        for (int j = 0; j < 4; j++)
            wr4[j] = (const float4*)(W + (size_t)(row + j) * D);
        const float4* x0 = (const float4*)s_in[0];
        const float4* x1 = (const float4*)s_in[1];
        const float4* x2 = (const float4*)s_in[2];

        float acc[4][3];
        #pragma unroll
        for (int j = 0; j < 4; j++)
            #pragma unroll
            for (int b = 0; b < 3; b++) acc[j][b] = 0.f;

        #pragma unroll
        for (int it = 0; it < 16; it++) {
            const int idx = it * 32 + l;
            float4 v0 = x0[idx], v1 = x1[idx], v2 = x2[idx];
            #pragma unroll
            for (int j = 0; j < 4; j++) {
                float4 wv = wr4[j][idx];
                acc[j][0] += wv.x*v0.x + wv.y*v0.y + wv.z*v0.z + wv.w*v0.w;
                acc[j][1] += wv.x*v1.x + wv.y*v1.y + wv.z*v1.z + wv.w*v1.w;
                acc[j][2] += wv.x*v2.x + wv.y*v2.y + wv.z*v2.z + wv.w*v2.w;
            }
        }
        #pragma unroll
        for (int j = 0; j < 4; j++) {
            float r0 = warp_sum(acc[j][0]);
            float r1 = warp_sum(acc[j][1]);
            float r2 = warp_sum(acc[j][2]);
            if (l == 0) {
                const float bv = bias[row + j];
                g_u[which][0][row + j] = r0 + bv;
                g_u[which][1][row + j] = r1 + bv;
                g_u[which][2][row + j] = r2 + bv;
            }
        }
    }
    grid_bar();

    // ===================== Phase C: dbc = dbc_w @ u (64 rows) ===============
    if (blk < 64) {
        const int e = blk;
        const float4* w4 = (const float4*)(Wdbc + (size_t)e * D);
        const float4* u4 = (const float4*)&g_u[0][0][0];  // 6 vecs x 512 float4

        float acc[6];
        #pragma unroll
        for (int v = 0; v < 6; v++) acc[v] = 0.f;
        #pragma unroll
        for (int half = 0; half < 2; half++) {
            const int idx = half * NTHR + tid;
            float4 wv = w4[idx];
            #pragma unroll
            for (int v = 0; v < 6; v++) {
                float4 uv = u4[v * 512 + idx];
                acc[v] += wv.x*uv.x + wv.y*uv.y + wv.z*uv.z + wv.w*uv.w;
            }
        }
        #pragma unroll
        for (int v = 0; v < 6; v++) acc[v] = warp_sum(acc[v]);
        if (l == 0) {
            #pragma unroll
            for (int v = 0; v < 6; v++) red[w][v] = acc[v];
        }
        __syncthreads();
        if (tid < 6) {
            float s = 0.f;
            #pragma unroll
            for (int i = 0; i < 8; i++) s += red[i][tid];
            (&g_dbc[0][0][0])[tid * 64 + e] = s;
        }
    }
    grid_bar();

    // ===================== Phase D: delta / gate / residual =================
    {
        for (int i = tid; i < 2 * 3 * 64; i += NTHR)
            (&s_dbc[0][0][0])[i] = (&g_dbc[0][0][0])[i];
        __syncthreads();
        if (tid < 6) {
            const int ww = tid / 3, b = tid % 3;
            float s = 0.f;
            #pragma unroll
            for (int n = 0; n < NST; n++)
                s += s_dbc[ww][b][RNK + n] * s_dbc[ww][b][RNK + NST + n];
            s_bc[ww][b] = s;
        }
        __syncthreads();

        // warp-per-d, 2 d per warp: 128 blocks * 8 warps * 2 = 2048
        #pragma unroll
        for (int rep = 0; rep < 2; rep++) {
            const int d = blk * 16 + rep * 8 + w;
            const float wr = dtp_w[(size_t)d * RNK + l];

            float s_f[3], s_b[3];
            #pragma unroll
            for (int b = 0; b < 3; b++) {
                s_f[b] = warp_sum_all(wr * s_dbc[0][b][l]);
                s_b[b] = warp_sum_all(wr * s_dbc[1][b][l]);
            }
            if (l < 3) {
                const int b = l;
                const float tb = dtp_b[d];
                const float dpv = Dp[d];
                const float df = softplus_f(s_f[b] + tb);
                const float db = softplus_f(s_b[b] + tb);
                const float y = g_u[0][b][d] * (df * s_bc[0][b] + dpv)
                              + g_u[1][b][d] * (db * s_bc[1][b] + dpv);
                const float z = g_z1[b][d];
                const float si = z / (1.f + expf(-z));
                out[b * D + d] = y * si + x[b * D + d];
            }
        }
    }
}

// ---------------------------------------------------------------------------
extern "C" void kernel_launch(void* const* d_in, const int* in_sizes, int n_in,
                              void* d_out, int out_size) {
    const float* x    = (const float*)d_in[0];
    const float* ng   = (const float*)d_in[1]  + (size_t)LAYER * D;
    const float* nb   = (const float*)d_in[2]  + (size_t)LAYER * D;
    const float* pw   = (const float*)d_in[3]  + (size_t)LAYER * D * D;
    const float* pb   = (const float*)d_in[4]  + (size_t)LAYER * D;
    const float* fw   = (const float*)d_in[5]  + (size_t)LAYER * D * D;
    const float* fb   = (const float*)d_in[6]  + (size_t)LAYER * D;
    const float* bw   = (const float*)d_in[7]  + (size_t)LAYER * D * D;
    const float* bb   = (const float*)d_in[8]  + (size_t)LAYER * D;
    const float* dbcw = (const float*)d_in[9]  + (size_t)LAYER * (RNK + 2 * NST) * D;
    const float* dtpw = (const float*)d_in[10] + (size_t)LAYER * D * RNK;
    const float* dtpb = (const float*)d_in[11] + (size_t)LAYER * D;
    // d_in[12] = A_log : unused (seq len 1, h0 = 0 -> dA*h term vanishes)
    const float* Dp   = (const float*)d_in[13] + (size_t)LAYER * D;
    float* out = (float*)d_out;

    k_all<<<GRID, NTHR>>>(x, ng, nb, pw, pb, fw, fb, bw, bb,
                          dbcw, dtpw, dtpb, Dp, out);
}

// round 5
// speedup vs baseline: 1.1792x; 1.1792x over previous
#include <cuda_runtime.h>
#include <math.h>

#define D      2048
#define RNK    32
#define NST    16
#define LAYER  11
#define GRID   128
#define NTHR   1024
#define NWARP  32

// Scratch (device globals; persist across graph replays)
__device__ float g_z1[3][D];
__device__ float g_u[2][3][D];               // [0]=f (fconv), [1]=bw (bconv)
__device__ float g_dbc[2][3][64];
__device__ unsigned long long g_bar;          // monotonic grid-barrier counter

__device__ __forceinline__ float warp_sum(float v) {     // result in lane 0
    v += __shfl_down_sync(0xffffffffu, v, 16);
    v += __shfl_down_sync(0xffffffffu, v, 8);
    v += __shfl_down_sync(0xffffffffu, v, 4);
    v += __shfl_down_sync(0xffffffffu, v, 2);
    v += __shfl_down_sync(0xffffffffu, v, 1);
    return v;
}
__device__ __forceinline__ float warp_sum_all(float v) {  // result in ALL lanes
    v += __shfl_xor_sync(0xffffffffu, v, 16);
    v += __shfl_xor_sync(0xffffffffu, v, 8);
    v += __shfl_xor_sync(0xffffffffu, v, 4);
    v += __shfl_xor_sync(0xffffffffu, v, 2);
    v += __shfl_xor_sync(0xffffffffu, v, 1);
    return v;
}

// Grid barrier: monotonic counter, round-up target. Replay-safe (never resets).
// GRID=128 blocks of 1024 thr, 1 per SM on 148 SMs -> all co-resident.
__device__ __forceinline__ void grid_bar() {
    __syncthreads();
    if (threadIdx.x == 0) {
        __threadfence();
        unsigned long long my = atomicAdd(&g_bar, 1ull) + 1ull;
        unsigned long long target = ((my + (GRID - 1ull)) / GRID) * GRID;
        volatile unsigned long long* p = (volatile unsigned long long*)&g_bar;
        while (*p < target) { }
        __threadfence();
    }
    __syncthreads();
}

__device__ __forceinline__ float softplus_f(float v) {
    return fmaxf(v, 0.f) + log1pf(expf(-fabsf(v)));
}

// ---------------------------------------------------------------------------
// One persistent kernel, 32 warps/SM for memory-level parallelism.
// ---------------------------------------------------------------------------
__global__ void __launch_bounds__(NTHR, 1) k_all(
        const float* __restrict__ x,
        const float* __restrict__ gam,
        const float* __restrict__ bet,
        const float* __restrict__ Wp,  const float* __restrict__ bp,
        const float* __restrict__ Wf,  const float* __restrict__ bf,
        const float* __restrict__ Wb,  const float* __restrict__ bb_,
        const float* __restrict__ Wdbc,
        const float* __restrict__ dtp_w,
        const float* __restrict__ dtp_b,
        const float* __restrict__ Dp,
        float* __restrict__ out) {
    __shared__ float s_in[3][D];          // 24 KB (xn, then z1)
    __shared__ float red[NWARP][6];
    __shared__ float s_part[NWARP][3];
    __shared__ float mu_s[3], inv_s[3];
    __shared__ float s_dbc[2][3][64];
    __shared__ float s_bc[2][3];

    const int tid = threadIdx.x;
    const int w   = tid >> 5;
    const int l   = tid & 31;
    const int blk = blockIdx.x;

    // ===================== Phase A: layernorm + proj ========================
    {
        float sm[3] = {0.f, 0.f, 0.f}, sq[3] = {0.f, 0.f, 0.f};
        #pragma unroll
        for (int rep = 0; rep < 2; rep++) {
            const int i = rep * NTHR + tid;
            #pragma unroll
            for (int b = 0; b < 3; b++) {
                float v = x[b * D + i];
                s_in[b][i] = v;
                sm[b] += v;
                sq[b] += v * v;
            }
        }
        #pragma unroll
        for (int b = 0; b < 3; b++) { sm[b] = warp_sum(sm[b]); sq[b] = warp_sum(sq[b]); }
        if (l == 0) {
            #pragma unroll
            for (int b = 0; b < 3; b++) { red[w][b] = sm[b]; red[w][3 + b] = sq[b]; }
        }
        __syncthreads();
        if (tid < 3) {
            float S = 0.f, Q = 0.f;
            #pragma unroll
            for (int i = 0; i < NWARP; i++) { S += red[i][tid]; Q += red[i][3 + tid]; }
            float mu = S * (1.f / D);
            float var = Q * (1.f / D) - mu * mu;
            mu_s[tid] = mu;
            inv_s[tid] = rsqrtf(var + 1e-5f);
        }
        __syncthreads();
        const float m0 = mu_s[0], m1 = mu_s[1], m2 = mu_s[2];
        const float i0 = inv_s[0], i1 = inv_s[1], i2 = inv_s[2];
        #pragma unroll
        for (int rep = 0; rep < 2; rep++) {
            const int i = rep * NTHR + tid;
            const float g = gam[i], be = bet[i];
            s_in[0][i] = (s_in[0][i] - m0) * i0 * g + be;
            s_in[1][i] = (s_in[1][i] - m1) * i1 * g + be;
            s_in[2][i] = (s_in[2][i] - m2) * i2 * g + be;
        }
        __syncthreads();

        // half-row per warp: 32 warps -> 16 rows/block -> 2048 rows
        const int rw   = w >> 1;                 // local row 0..15
        const int half = w & 1;                  // which half of the dot
        const int row  = blk * 16 + rw;
        const float4* wp4 = (const float4*)(Wp + (size_t)row * D) + half * 256;
        const float4* x0 = (const float4*)s_in[0] + half * 256;
        const float4* x1 = (const float4*)s_in[1] + half * 256;
        const float4* x2 = (const float4*)s_in[2] + half * 256;
        float a0 = 0.f, a1 = 0.f, a2 = 0.f;
        #pragma unroll
        for (int it = 0; it < 8; it++) {
            const int idx = it * 32 + l;
            float4 wv = wp4[idx];
            float4 v0 = x0[idx], v1 = x1[idx], v2 = x2[idx];
            a0 += wv.x*v0.x + wv.y*v0.y + wv.z*v0.z + wv.w*v0.w;
            a1 += wv.x*v1.x + wv.y*v1.y + wv.z*v1.z + wv.w*v1.w;
            a2 += wv.x*v2.x + wv.y*v2.y + wv.z*v2.z + wv.w*v2.w;
        }
        a0 = warp_sum(a0); a1 = warp_sum(a1); a2 = warp_sum(a2);
        if (l == 0) { s_part[w][0] = a0; s_part[w][1] = a1; s_part[w][2] = a2; }
        __syncthreads();
        if (tid < 48) {   // 16 rows x 3 batches
            const int rr = tid / 3, b = tid % 3;
            const int row_g = blk * 16 + rr;
            g_z1[b][row_g] = s_part[2 * rr][b] + s_part[2 * rr + 1][b] + bp[row_g];
        }
    }
    grid_bar();

    // ===================== Phase B: f/b conv matvecs ========================
    {
        const float* src = &g_z1[0][0];
        #pragma unroll
        for (int rep = 0; rep < 6; rep++)
            (&s_in[0][0])[rep * NTHR + tid] = src[rep * NTHR + tid];
        __syncthreads();

        // 1 full row per warp: 128 blocks x 32 warps = 4096 rows
        const int which = (blk >= 64) ? 1 : 0;
        const int row = (blk & 63) * 32 + w;
        const float* W = which ? Wb : Wf;
        const float* bias = which ? bb_ : bf;

        const float4* w4 = (const float4*)(W + (size_t)row * D);
        const float4* x0 = (const float4*)s_in[0];
        const float4* x1 = (const float4*)s_in[1];
        const float4* x2 = (const float4*)s_in[2];
        float a0 = 0.f, a1 = 0.f, a2 = 0.f;
        #pragma unroll
        for (int it = 0; it < 16; it++) {
            const int idx = it * 32 + l;
            float4 wv = w4[idx];
            float4 v0 = x0[idx], v1 = x1[idx], v2 = x2[idx];
            a0 += wv.x*v0.x + wv.y*v0.y + wv.z*v0.z + wv.w*v0.w;
            a1 += wv.x*v1.x + wv.y*v1.y + wv.z*v1.z + wv.w*v1.w;
            a2 += wv.x*v2.x + wv.y*v2.y + wv.z*v2.z + wv.w*v2.w;
        }
        a0 = warp_sum(a0); a1 = warp_sum(a1); a2 = warp_sum(a2);
        if (l == 0) {
            const float bv = bias[row];
            g_u[which][0][row] = a0 + bv;
            g_u[which][1][row] = a1 + bv;
            g_u[which][2][row] = a2 + bv;
        }
    }
    grid_bar();

    // ===================== Phase C: dbc = dbc_w @ u (64 rows) ===============
    if (blk < 64) {
        const int e = blk;
        const float4* w4 = (const float4*)(Wdbc + (size_t)e * D);
        const float4* u4 = (const float4*)&g_u[0][0][0];   // 6 vecs x 512 float4

        // tid -> (group of 3 vectors, float4 index)
        const int grp = tid >> 9;          // 0: vecs 0-2, 1: vecs 3-5
        const int idx = tid & 511;
        float4 wv = w4[idx];
        float acc[3];
        #pragma unroll
        for (int v = 0; v < 3; v++) {
            float4 uv = u4[(grp * 3 + v) * 512 + idx];
            acc[v] = wv.x*uv.x + wv.y*uv.y + wv.z*uv.z + wv.w*uv.w;
        }
        #pragma unroll
        for (int v = 0; v < 3; v++) acc[v] = warp_sum(acc[v]);
        if (l == 0) {
            #pragma unroll
            for (int v = 0; v < 3; v++) red[w][v] = acc[v];
        }
        __syncthreads();
        if (tid < 6) {
            const int base = (tid / 3) * 16;   // warps 0-15 grp0, 16-31 grp1
            float s = 0.f;
            #pragma unroll
            for (int i = 0; i < 16; i++) s += red[base + i][tid % 3];
            (&g_dbc[0][0][0])[tid * 64 + e] = s;
        }
    }
    grid_bar();

    // ===================== Phase D: delta / gate / residual =================
    {
        if (tid < 2 * 3 * 64)
            (&s_dbc[0][0][0])[tid] = (&g_dbc[0][0][0])[tid];
        __syncthreads();
        if (tid < 6) {
            const int ww = tid / 3, b = tid % 3;
            float s = 0.f;
            #pragma unroll
            for (int n = 0; n < NST; n++)
                s += s_dbc[ww][b][RNK + n] * s_dbc[ww][b][RNK + NST + n];
            s_bc[ww][b] = s;
        }
        __syncthreads();

        // warp-per-d: warps 0..15 of each block -> 2048 d's
        if (w < 16) {
            const int d = blk * 16 + w;
            const float wr = dtp_w[(size_t)d * RNK + l];
            float s_f[3], s_b[3];
            #pragma unroll
            for (int b = 0; b < 3; b++) {
                s_f[b] = warp_sum_all(wr * s_dbc[0][b][l]);
                s_b[b] = warp_sum_all(wr * s_dbc[1][b][l]);
            }
            if (l < 3) {
                const int b = l;
                const float tb = dtp_b[d];
                const float dpv = Dp[d];
                const float df = softplus_f(s_f[b] + tb);
                const float db = softplus_f(s_b[b] + tb);
                const float y = g_u[0][b][d] * (df * s_bc[0][b] + dpv)
                              + g_u[1][b][d] * (db * s_bc[1][b] + dpv);
                const float z = g_z1[b][d];
                const float si = z / (1.f + expf(-z));
                out[b * D + d] = y * si + x[b * D + d];
            }
        }
    }
}

// ---------------------------------------------------------------------------
extern "C" void kernel_launch(void* const* d_in, const int* in_sizes, int n_in,
                              void* d_out, int out_size) {
    const float* x    = (const float*)d_in[0];
    const float* ng   = (const float*)d_in[1]  + (size_t)LAYER * D;
    const float* nb   = (const float*)d_in[2]  + (size_t)LAYER * D;
    const float* pw   = (const float*)d_in[3]  + (size_t)LAYER * D * D;
    const float* pb   = (const float*)d_in[4]  + (size_t)LAYER * D;
    const float* fw   = (const float*)d_in[5]  + (size_t)LAYER * D * D;
    const float* fb   = (const float*)d_in[6]  + (size_t)LAYER * D;
    const float* bw   = (const float*)d_in[7]  + (size_t)LAYER * D * D;
    const float* bb   = (const float*)d_in[8]  + (size_t)LAYER * D;
    const float* dbcw = (const float*)d_in[9]  + (size_t)LAYER * (RNK + 2 * NST) * D;
    const float* dtpw = (const float*)d_in[10] + (size_t)LAYER * D * RNK;
    const float* dtpb = (const float*)d_in[11] + (size_t)LAYER * D;
    // d_in[12] = A_log : unused (seq len 1, h0 = 0 -> dA*h term vanishes)
    const float* Dp   = (const float*)d_in[13] + (size_t)LAYER * D;
    float* out = (float*)d_out;

    k_all<<<GRID, NTHR>>>(x, ng, nb, pw, pb, fw, fb, bw, bb,
                          dbcw, dtpw, dtpb, Dp, out);
}